// round 12
// baseline (speedup 1.0000x reference)
#include <cuda_runtime.h>
#include <cstdint>
#include <math.h>

#define NTOK 4096
#define DMODEL 1024
#define NEXP 8
#define DFF 4096

#define BM 128
#define BN 64
#define BK 32

#define PA 36
#define PB 36
#define G1_BG_OFF (128 * PA)               // 4608 floats
#define G1_BU_OFF (G1_BG_OFF + 64 * PB)    // 6912
#define G1_STAGE_F (G1_BU_OFF + 64 * PB)   // 9216 floats = 36864 B
#define G2_B_OFF (128 * PA)                // 4608
#define G2_STAGE_F (G2_B_OFF + 64 * PB)    // 6912 floats = 27648 B
#define G1_STAGES 3
#define G2_STAGES 4
#define G1_SMEM (G1_STAGES * G1_STAGE_F * 4)   // 110592 B
#define G2_SMEM (G2_STAGES * G2_STAGE_F * 4)   // 110592 B

// ---------------- scratch (static device globals; no allocation) ----------------
__device__ int   g_counts[NEXP];
__device__ int   g_offsets[NEXP + 1];
__device__ int   g_cursor[NEXP];
__device__ int   g_slot_e[NTOK * 2];
__device__ float g_slot_w[NTOK * 2];
__device__ int   g_row_token[NTOK * 2];
__device__ float g_row_w[NTOK * 2];

__device__ float g_x_p [(size_t)NTOK * DMODEL];          // tf32, k-major (plain)
__device__ float g_wg_p[(size_t)NEXP * DFF * DMODEL];    // tf32, n-major [e][n][k]
__device__ float g_wu_p[(size_t)NEXP * DFF * DMODEL];    // tf32, n-major [e][n][k]
__device__ float g_wd_p[(size_t)NEXP * DMODEL * DFF];    // tf32, n-major [e][n][k]
__device__ float g_H   [(size_t)NTOK * 2 * DFF];         // tf32, k-major (plain)

// ---------------- helpers ----------------
__device__ __forceinline__ float qtf(float f) {
    uint32_t r;
    asm("cvt.rna.tf32.f32 %0, %1;" : "=r"(r) : "f"(f));
    return __uint_as_float(r);
}

__device__ __forceinline__ void mma_tf32(float c[4], const uint32_t a[4], const uint32_t b[2]) {
    asm volatile(
        "mma.sync.aligned.m16n8k8.row.col.f32.tf32.tf32.f32 "
        "{%0,%1,%2,%3}, {%4,%5,%6,%7}, {%8,%9}, {%0,%1,%2,%3};"
        : "+f"(c[0]), "+f"(c[1]), "+f"(c[2]), "+f"(c[3])
        : "r"(a[0]), "r"(a[1]), "r"(a[2]), "r"(a[3]), "r"(b[0]), "r"(b[1]));
}

__device__ __forceinline__ void ldsm4(uint32_t* r, uint32_t addr) {
    asm volatile("ldmatrix.sync.aligned.m8n8.x4.shared.b16 {%0,%1,%2,%3}, [%4];"
        : "=r"(r[0]), "=r"(r[1]), "=r"(r[2]), "=r"(r[3]) : "r"(addr));
}

__device__ __forceinline__ void cp16(void* dst, const void* src) {
    uint32_t d = (uint32_t)__cvta_generic_to_shared(dst);
    asm volatile("cp.async.cg.shared.global [%0], [%1], 16;" :: "r"(d), "l"(src));
}
#define CP_COMMIT() asm volatile("cp.async.commit_group;" ::: "memory")
#define CP_WAIT(n)  asm volatile("cp.async.wait_group %0;" :: "n"(n) : "memory")

// ---------------- pack: tf32-convert + transpose weights to n-major ----------------
__global__ void pack_w_kernel(const float* __restrict__ wg,
                              const float* __restrict__ wu,
                              const float* __restrict__ wd) {
    __shared__ float tg[32][33];
    __shared__ float tu[32][33];
    int z = blockIdx.z;
    int tx = threadIdx.x, ty = threadIdx.y;
    if (z == 0 && blockIdx.x == 0 && blockIdx.y == 0 && ty == 0 && tx < NEXP)
        g_counts[tx] = 0;

    if (z < 8) {
        size_t e = z;
        size_t kb = (size_t)blockIdx.y * 32, nb = (size_t)blockIdx.x * 32;
        #pragma unroll
        for (int i = 0; i < 4; i++) {
            size_t k = kb + ty + i * 8;
            tg[ty + i * 8][tx] = qtf(wg[(e * DMODEL + k) * DFF + nb + tx]);
            tu[ty + i * 8][tx] = qtf(wu[(e * DMODEL + k) * DFF + nb + tx]);
        }
        __syncthreads();
        #pragma unroll
        for (int i = 0; i < 4; i++) {
            size_t n = nb + ty + i * 8;
            g_wg_p[(e * DFF + n) * DMODEL + kb + tx] = tg[tx][ty + i * 8];
            g_wu_p[(e * DFF + n) * DMODEL + kb + tx] = tu[tx][ty + i * 8];
        }
    } else {
        size_t e = z - 8;
        size_t kb = (size_t)blockIdx.x * 32, nb = (size_t)blockIdx.y * 32;
        #pragma unroll
        for (int i = 0; i < 4; i++) {
            size_t k = kb + ty + i * 8;
            tg[ty + i * 8][tx] = qtf(wd[(e * DFF + k) * DMODEL + nb + tx]);
        }
        __syncthreads();
        #pragma unroll
        for (int i = 0; i < 4; i++) {
            size_t n = nb + ty + i * 8;
            g_wd_p[(e * DMODEL + n) * DFF + kb + tx] = tg[tx][ty + i * 8];
        }
    }
}

// ---------------- router (+ x tf32 pack): one warp per token ----------------
__global__ void router_kernel(const float* __restrict__ x,
                              const float* __restrict__ rw,
                              const float* __restrict__ rb,
                              float* __restrict__ probs_out,
                              float* __restrict__ idx_out) {
    {
        size_t base = (size_t)blockIdx.x * 4 * DMODEL;
        const float4* src = (const float4*)(x + base);
        float4* dst = (float4*)(g_x_p + base);
        for (int i = threadIdx.x; i < 4 * DMODEL / 4; i += 128) {
            float4 v = src[i];
            dst[i] = make_float4(qtf(v.x), qtf(v.y), qtf(v.z), qtf(v.w));
        }
    }

    int warp = (blockIdx.x * blockDim.x + threadIdx.x) >> 5;
    int lane = threadIdx.x & 31;
    if (warp >= NTOK) return;
    const float* xr = x + (size_t)warp * DMODEL;

    float acc[NEXP];
    #pragma unroll
    for (int e = 0; e < NEXP; e++) acc[e] = 0.f;

    for (int d = lane; d < DMODEL; d += 32) {
        float xv = xr[d];
        const float4* w4 = reinterpret_cast<const float4*>(rw + (size_t)d * NEXP);
        float4 w0 = w4[0], w1 = w4[1];
        acc[0] += xv * w0.x; acc[1] += xv * w0.y; acc[2] += xv * w0.z; acc[3] += xv * w0.w;
        acc[4] += xv * w1.x; acc[5] += xv * w1.y; acc[6] += xv * w1.z; acc[7] += xv * w1.w;
    }
    #pragma unroll
    for (int e = 0; e < NEXP; e++) {
        #pragma unroll
        for (int o = 16; o > 0; o >>= 1) acc[e] += __shfl_xor_sync(0xffffffffu, acc[e], o);
    }

    if (lane == 0) {
        float lg[NEXP];
        #pragma unroll
        for (int e = 0; e < NEXP; e++) lg[e] = acc[e] + rb[e];

        float m = lg[0];
        #pragma unroll
        for (int e = 1; e < NEXP; e++) m = fmaxf(m, lg[e]);
        float s = 0.f, p[NEXP];
        #pragma unroll
        for (int e = 0; e < NEXP; e++) { p[e] = expf(lg[e] - m); s += p[e]; }
        float inv = 1.f / s;
        #pragma unroll
        for (int e = 0; e < NEXP; e++) probs_out[(size_t)warp * NEXP + e] = p[e] * inv;

        int i0 = 0;
        #pragma unroll
        for (int e = 1; e < NEXP; e++) if (lg[e] > lg[i0]) i0 = e;
        int i1 = -1;
        #pragma unroll
        for (int e = 0; e < NEXP; e++) {
            if (e == i0) continue;
            if (i1 < 0 || lg[e] > lg[i1]) i1 = e;
        }
        float p0 = 1.f / (1.f + expf(lg[i1] - lg[i0]));
        float p1 = 1.f - p0;

        idx_out[warp * 2 + 0] = (float)i0;
        idx_out[warp * 2 + 1] = (float)i1;
        g_slot_e[warp * 2 + 0] = i0;
        g_slot_e[warp * 2 + 1] = i1;
        g_slot_w[warp * 2 + 0] = p0;
        g_slot_w[warp * 2 + 1] = p1;
        atomicAdd(&g_counts[i0], 1);
        atomicAdd(&g_counts[i1], 1);
    }
}

// ---------------- fused scan + list build ----------------
__global__ void finalize_kernel() {
    if (threadIdx.x == 0) {
        int off = 0;
        for (int e = 0; e < NEXP; e++) {
            g_offsets[e] = off;
            g_cursor[e]  = off;
            off += g_counts[e];
        }
        g_offsets[NEXP] = off;
    }
    __syncthreads();
    for (int t = threadIdx.x; t < NTOK; t += blockDim.x) {
        #pragma unroll
        for (int s = 0; s < 2; s++) {
            int e = g_slot_e[t * 2 + s];
            int pos = atomicAdd(&g_cursor[e], 1);
            g_row_token[pos] = t;
            g_row_w[pos] = g_slot_w[t * 2 + s];
        }
    }
}

// ---------------- GEMM1: H = silu(Xe@Wg+bg) * (Xe@Wu+bu) ----------------
// ldmatrix fragments, BK=32, 3-stage cp.async pipeline, ONE barrier per 4 ks-steps.
__global__ __launch_bounds__(256, 2)
void gemm1_kernel(const float* __restrict__ bg, const float* __restrict__ bu) {
    extern __shared__ float smem[];
    int e = blockIdx.z;
    int off = g_offsets[e];
    int ne = g_offsets[e + 1] - off;
    int mbase = blockIdx.x * BM;
    if (mbase >= ne) return;
    int n0 = blockIdx.y * BN;

    int tid = threadIdx.x;
    int lane = tid & 31, warp = tid >> 5;
    int wm = (warp & 3) * 32;
    int wn = (warp >> 2) * 32;

    // loaders: A row ra (0..127), k-half ah (0/16); B n-row rb8 (0..63), 8-col group
    int ra = tid >> 1;
    int ah = (tid & 1) * 16;
    int ar = mbase + ra;
    const float* gA  = g_x_p + (size_t)g_row_token[off + (ar < ne ? ar : 0)] * DMODEL + ah;
    int rb8 = tid >> 2;
    int bc  = (tid & 3) * 8;
    const float* gBg = g_wg_p + ((size_t)e * DFF + n0 + rb8) * DMODEL + bc;
    const float* gBu = g_wu_p + ((size_t)e * DFF + n0 + rb8) * DMODEL + bc;
    int daA = ra * PA + ah;
    int daB = rb8 * PB + bc;

    // ldmatrix lane addresses
    uint32_t sbase = (uint32_t)__cvta_generic_to_shared(smem);
    int rowa = ((lane >> 3) & 1) * 8 + (lane & 7);
    int koffa = (lane >> 4) * 4;
    int rowb = (lane >> 4) * 8 + (lane & 7);
    int koffb = ((lane >> 3) & 1) * 4;
    uint32_t aAddr[2], bgAddr[2], buAddr[2];
    #pragma unroll
    for (int mi = 0; mi < 2; mi++)
        aAddr[mi] = sbase + ((wm + mi * 16 + rowa) * PA + koffa) * 4;
    #pragma unroll
    for (int p = 0; p < 2; p++) {
        bgAddr[p] = sbase + (G1_BG_OFF + (wn + p * 16 + rowb) * PB + koffb) * 4;
        buAddr[p] = sbase + (G1_BU_OFF + (wn + p * 16 + rowb) * PB + koffb) * 4;
    }

    float accG[2][4][4], accU[2][4][4];
    #pragma unroll
    for (int mi = 0; mi < 2; mi++)
        #pragma unroll
        for (int ni = 0; ni < 4; ni++)
            #pragma unroll
            for (int q = 0; q < 4; q++) { accG[mi][ni][q] = 0.f; accU[mi][ni][q] = 0.f; }

    const int KT = DMODEL / BK;   // 32

    #define G1_PREFETCH(kt, st) do {                                   \
        float* b = smem + (st) * G1_STAGE_F;                           \
        const float* a_ = gA + (kt) * BK;                              \
        cp16(b + daA,      a_);                                        \
        cp16(b + daA + 4,  a_ + 4);                                    \
        cp16(b + daA + 8,  a_ + 8);                                    \
        cp16(b + daA + 12, a_ + 12);                                   \
        cp16(b + G1_BG_OFF + daB,     gBg + (kt) * BK);                \
        cp16(b + G1_BG_OFF + daB + 4, gBg + (kt) * BK + 4);            \
        cp16(b + G1_BU_OFF + daB,     gBu + (kt) * BK);                \
        cp16(b + G1_BU_OFF + daB + 4, gBu + (kt) * BK + 4);            \
        CP_COMMIT();                                                   \
    } while (0)

    G1_PREFETCH(0, 0);
    G1_PREFETCH(1, 1);

    for (int kt = 0; kt < KT; kt++) {
        CP_WAIT(1);
        __syncthreads();
        if (kt + 2 < KT) G1_PREFETCH(kt + 2, (kt + 2) % G1_STAGES);
        else CP_COMMIT();   // keep group count exact for CP_WAIT(1)

        uint32_t so = (uint32_t)((kt % G1_STAGES) * G1_STAGE_F * 4);
        #pragma unroll
        for (int ks = 0; ks < 4; ks++) {
            uint32_t kso = so + ks * 32;
            uint32_t af[2][4], bgf[2][4], buf[2][4];
            ldsm4(af[0], aAddr[0] + kso);
            ldsm4(af[1], aAddr[1] + kso);
            ldsm4(bgf[0], bgAddr[0] + kso);
            ldsm4(bgf[1], bgAddr[1] + kso);
            ldsm4(buf[0], buAddr[0] + kso);
            ldsm4(buf[1], buAddr[1] + kso);
            #pragma unroll
            for (int mi = 0; mi < 2; mi++)
                #pragma unroll
                for (int p = 0; p < 2; p++) {
                    mma_tf32(accG[mi][2 * p],     af[mi], &bgf[p][0]);
                    mma_tf32(accG[mi][2 * p + 1], af[mi], &bgf[p][2]);
                    mma_tf32(accU[mi][2 * p],     af[mi], &buf[p][0]);
                    mma_tf32(accU[mi][2 * p + 1], af[mi], &buf[p][2]);
                }
        }
    }
    #undef G1_PREFETCH

    // epilogue: silu(g)*u -> tf32 H (plain layout)
    const float* bgp = bg + (size_t)e * DFF + n0;
    const float* bup = bu + (size_t)e * DFF + n0;
    #pragma unroll
    for (int mi = 0; mi < 2; mi++) {
        int r0 = mbase + wm + mi * 16 + (lane >> 2);
        #pragma unroll
        for (int ni = 0; ni < 4; ni++) {
            int nc = wn + ni * 8 + (lane & 3) * 2;
            float bg0 = bgp[nc], bg1 = bgp[nc + 1];
            float bu0 = bup[nc], bu1 = bup[nc + 1];
            if (r0 < ne) {
                size_t base = (size_t)(off + r0) * DFF + n0 + nc;
                float g = accG[mi][ni][0] + bg0, u = accU[mi][ni][0] + bu0;
                g_H[base] = qtf((g / (1.f + expf(-g))) * u);
                g = accG[mi][ni][1] + bg1; u = accU[mi][ni][1] + bu1;
                g_H[base + 1] = qtf((g / (1.f + expf(-g))) * u);
            }
            if (r0 + 8 < ne) {
                size_t base = (size_t)(off + r0 + 8) * DFF + n0 + nc;
                float g = accG[mi][ni][2] + bg0, u = accU[mi][ni][2] + bu0;
                g_H[base] = qtf((g / (1.f + expf(-g))) * u);
                g = accG[mi][ni][3] + bg1; u = accU[mi][ni][3] + bu1;
                g_H[base + 1] = qtf((g / (1.f + expf(-g))) * u);
            }
        }
    }
}

// ---------------- GEMM2: out[token] += w * (H_e @ Wd_e + bd) ----------------
// ldmatrix fragments, BK=32, 4-stage cp.async pipeline (prefetch 3 ahead), one barrier/iter.
__global__ __launch_bounds__(256, 2)
void gemm2_kernel(const float* __restrict__ bd, float* __restrict__ out) {
    extern __shared__ float smem[];
    int e = blockIdx.z;
    int off = g_offsets[e];
    int ne = g_offsets[e + 1] - off;
    int mbase = blockIdx.x * BM;
    if (mbase >= ne) return;
    int n0 = blockIdx.y * BN;

    int tid = threadIdx.x;
    int lane = tid & 31, warp = tid >> 5;
    int wm = (warp & 3) * 32;
    int wn = (warp >> 2) * 32;

    int ra = tid >> 1;
    int ah = (tid & 1) * 16;
    int ar = mbase + ra;
    const float* gA = g_H + (size_t)(off + (ar < ne ? ar : 0)) * DFF + ah;
    int rb8 = tid >> 2;
    int bc  = (tid & 3) * 8;
    const float* gB = g_wd_p + ((size_t)e * DMODEL + n0 + rb8) * DFF + bc;
    int daA = ra * PA + ah;
    int daB = rb8 * PB + bc;

    uint32_t sbase = (uint32_t)__cvta_generic_to_shared(smem);
    int rowa = ((lane >> 3) & 1) * 8 + (lane & 7);
    int koffa = (lane >> 4) * 4;
    int rowb = (lane >> 4) * 8 + (lane & 7);
    int koffb = ((lane >> 3) & 1) * 4;
    uint32_t aAddr[2], bAddr[2];
    #pragma unroll
    for (int mi = 0; mi < 2; mi++)
        aAddr[mi] = sbase + ((wm + mi * 16 + rowa) * PA + koffa) * 4;
    #pragma unroll
    for (int p = 0; p < 2; p++)
        bAddr[p] = sbase + (G2_B_OFF + (wn + p * 16 + rowb) * PB + koffb) * 4;

    float acc[2][4][4];
    #pragma unroll
    for (int mi = 0; mi < 2; mi++)
        #pragma unroll
        for (int ni = 0; ni < 4; ni++)
            #pragma unroll
            for (int q = 0; q < 4; q++) acc[mi][ni][q] = 0.f;

    const int KT = DFF / BK;   // 128

    #define G2_PREFETCH(kt, st) do {                                   \
        float* b = smem + (st) * G2_STAGE_F;                           \
        const float* a_ = gA + (kt) * BK;                              \
        cp16(b + daA,      a_);                                        \
        cp16(b + daA + 4,  a_ + 4);                                    \
        cp16(b + daA + 8,  a_ + 8);                                    \
        cp16(b + daA + 12, a_ + 12);                                   \
        cp16(b + G2_B_OFF + daB,     gB + (kt) * BK);                  \
        cp16(b + G2_B_OFF + daB + 4, gB + (kt) * BK + 4);              \
        CP_COMMIT();                                                   \
    } while (0)

    G2_PREFETCH(0, 0);
    G2_PREFETCH(1, 1);
    G2_PREFETCH(2, 2);

    for (int kt = 0; kt < KT; kt++) {
        CP_WAIT(2);
        __syncthreads();
        if (kt + 3 < KT) G2_PREFETCH(kt + 3, (kt + 3) % G2_STAGES);
        else CP_COMMIT();   // keep group count exact for CP_WAIT(2)

        uint32_t so = (uint32_t)((kt % G2_STAGES) * G2_STAGE_F * 4);
        #pragma unroll
        for (int ks = 0; ks < 4; ks++) {
            uint32_t kso = so + ks * 32;
            uint32_t af[2][4], bf[2][4];
            ldsm4(af[0], aAddr[0] + kso);
            ldsm4(af[1], aAddr[1] + kso);
            ldsm4(bf[0], bAddr[0] + kso);
            ldsm4(bf[1], bAddr[1] + kso);
            #pragma unroll
            for (int mi = 0; mi < 2; mi++)
                #pragma unroll
                for (int p = 0; p < 2; p++) {
                    mma_tf32(acc[mi][2 * p],     af[mi], &bf[p][0]);
                    mma_tf32(acc[mi][2 * p + 1], af[mi], &bf[p][2]);
                }
        }
    }
    #undef G2_PREFETCH

    // epilogue: weighted scatter-add into out
    const float* bdp = bd + (size_t)e * DMODEL + n0;
    #pragma unroll
    for (int mi = 0; mi < 2; mi++) {
        int r0 = mbase + wm + mi * 16 + (lane >> 2);
        #pragma unroll
        for (int ni = 0; ni < 4; ni++) {
            int nc = wn + ni * 8 + (lane & 3) * 2;
            float b0 = bdp[nc], b1 = bdp[nc + 1];
            if (r0 < ne) {
                int tokr = g_row_token[off + r0];
                float w = g_row_w[off + r0];
                float* op = out + (size_t)tokr * DMODEL + n0 + nc;
                atomicAdd(op,     w * (acc[mi][ni][0] + b0));
                atomicAdd(op + 1, w * (acc[mi][ni][1] + b1));
            }
            if (r0 + 8 < ne) {
                int tokr = g_row_token[off + r0 + 8];
                float w = g_row_w[off + r0 + 8];
                float* op = out + (size_t)tokr * DMODEL + n0 + nc;
                atomicAdd(op,     w * (acc[mi][ni][2] + b0));
                atomicAdd(op + 1, w * (acc[mi][ni][3] + b1));
            }
        }
    }
}

// ---------------- launch ----------------
extern "C" void kernel_launch(void* const* d_in, const int* in_sizes, int n_in,
                              void* d_out, int out_size) {
    const float* x  = (const float*)d_in[0];
    const float* rw = (const float*)d_in[1];
    const float* rb = (const float*)d_in[2];
    const float* wg = (const float*)d_in[3];
    const float* bg = (const float*)d_in[4];
    const float* wu = (const float*)d_in[5];
    const float* bu = (const float*)d_in[6];
    const float* wd = (const float*)d_in[7];
    const float* bd = (const float*)d_in[8];

    float* out   = (float*)d_out;
    float* probs = out + (size_t)NTOK * DMODEL;
    float* idx   = probs + (size_t)NTOK * NEXP;

    cudaFuncSetAttribute(gemm1_kernel, cudaFuncAttributeMaxDynamicSharedMemorySize, G1_SMEM);
    cudaFuncSetAttribute(gemm2_kernel, cudaFuncAttributeMaxDynamicSharedMemorySize, G2_SMEM);

    cudaMemsetAsync(out, 0, (size_t)NTOK * DMODEL * sizeof(float));
    pack_w_kernel<<<dim3(128, 32, 16), dim3(32, 8)>>>(wg, wu, wd);
    router_kernel<<<NTOK / 4, 128>>>(x, rw, rb, probs, idx);
    finalize_kernel<<<1, 256>>>();
    gemm1_kernel<<<dim3(NTOK / BM, DFF / BN, NEXP), 256, G1_SMEM>>>(bg, bu);
    gemm2_kernel<<<dim3(NTOK / BM, DMODEL / BN, NEXP), 256, G2_SMEM>>>(bd, out);
}

// round 13
// speedup vs baseline: 2.0618x; 2.0618x over previous
#include <cuda_runtime.h>
#include <cuda_fp16.h>
#include <cstdint>
#include <math.h>

#define NTOK 4096
#define DMODEL 1024
#define NEXP 8
#define DFF 4096

#define BM 128
#define BN 64
#define BK 32            // 32 halves = 64 B per row per tile

#define PHB 80           // bytes per smem row (40 halves); 80i mod 128 covers 8 disjoint 16B spans
#define G1_BG 10240      // A: 128*80
#define G1_BU 15360      // + Bg: 64*80
#define G1_STB 20480     // stage bytes
#define G2_BOFF 10240
#define G2_STB 15360
#define G1_STAGES 3
#define G2_STAGES 4
#define G1_SMEM (G1_STAGES * G1_STB)   // 61440
#define G2_SMEM (G2_STAGES * G2_STB)   // 61440

// ---------------- scratch (static device globals; no allocation) ----------------
__device__ int   g_counts[NEXP];
__device__ int   g_offsets[NEXP + 1];
__device__ int   g_cursor[NEXP];
__device__ int   g_slot_e[NTOK * 2];
__device__ float g_slot_w[NTOK * 2];
__device__ int   g_row_token[NTOK * 2];
__device__ float g_row_w[NTOK * 2];

__device__ __align__(16) __half g_x_h [(size_t)NTOK * DMODEL];          // fp16, k-major
__device__ __align__(16) __half g_wg_h[(size_t)NEXP * DFF * DMODEL];    // fp16, n-major [e][n][k]
__device__ __align__(16) __half g_wu_h[(size_t)NEXP * DFF * DMODEL];    // fp16, n-major [e][n][k]
__device__ __align__(16) __half g_wd_h[(size_t)NEXP * DMODEL * DFF];    // fp16, n-major [e][n][k]
__device__ __align__(16) __half g_H_h [(size_t)NTOK * 2 * DFF];         // fp16, k-major

// ---------------- helpers ----------------
__device__ __forceinline__ void mma_f16(float c[4], const uint32_t a[4], const uint32_t b[2]) {
    asm volatile(
        "mma.sync.aligned.m16n8k16.row.col.f32.f16.f16.f32 "
        "{%0,%1,%2,%3}, {%4,%5,%6,%7}, {%8,%9}, {%0,%1,%2,%3};"
        : "+f"(c[0]), "+f"(c[1]), "+f"(c[2]), "+f"(c[3])
        : "r"(a[0]), "r"(a[1]), "r"(a[2]), "r"(a[3]), "r"(b[0]), "r"(b[1]));
}

__device__ __forceinline__ void ldsm4(uint32_t* r, uint32_t addr) {
    asm volatile("ldmatrix.sync.aligned.m8n8.x4.shared.b16 {%0,%1,%2,%3}, [%4];"
        : "=r"(r[0]), "=r"(r[1]), "=r"(r[2]), "=r"(r[3]) : "r"(addr));
}

__device__ __forceinline__ void cp16(void* dst, const void* src) {
    uint32_t d = (uint32_t)__cvta_generic_to_shared(dst);
    asm volatile("cp.async.cg.shared.global [%0], [%1], 16;" :: "r"(d), "l"(src));
}
#define CP_COMMIT() asm volatile("cp.async.commit_group;" ::: "memory")
#define CP_WAIT(n)  asm volatile("cp.async.wait_group %0;" :: "n"(n) : "memory")

// ---------------- pack: fp16-convert + transpose weights to n-major ----------------
__global__ void pack_w_kernel(const float* __restrict__ wg,
                              const float* __restrict__ wu,
                              const float* __restrict__ wd) {
    __shared__ float tg[32][33];
    __shared__ float tu[32][33];
    int z = blockIdx.z;
    int tx = threadIdx.x, ty = threadIdx.y;
    if (z == 0 && blockIdx.x == 0 && blockIdx.y == 0 && ty == 0 && tx < NEXP)
        g_counts[tx] = 0;

    if (z < 8) {
        size_t e = z;
        size_t kb = (size_t)blockIdx.y * 32, nb = (size_t)blockIdx.x * 32;
        #pragma unroll
        for (int i = 0; i < 4; i++) {
            size_t k = kb + ty + i * 8;
            tg[ty + i * 8][tx] = wg[(e * DMODEL + k) * DFF + nb + tx];
            tu[ty + i * 8][tx] = wu[(e * DMODEL + k) * DFF + nb + tx];
        }
        __syncthreads();
        #pragma unroll
        for (int i = 0; i < 4; i++) {
            size_t n = nb + ty + i * 8;
            g_wg_h[(e * DFF + n) * DMODEL + kb + tx] = __float2half_rn(tg[tx][ty + i * 8]);
            g_wu_h[(e * DFF + n) * DMODEL + kb + tx] = __float2half_rn(tu[tx][ty + i * 8]);
        }
    } else {
        size_t e = z - 8;
        size_t kb = (size_t)blockIdx.x * 32, nb = (size_t)blockIdx.y * 32;
        #pragma unroll
        for (int i = 0; i < 4; i++) {
            size_t k = kb + ty + i * 8;
            tg[ty + i * 8][tx] = wd[(e * DFF + k) * DMODEL + nb + tx];
        }
        __syncthreads();
        #pragma unroll
        for (int i = 0; i < 4; i++) {
            size_t n = nb + ty + i * 8;
            g_wd_h[(e * DMODEL + n) * DFF + kb + tx] = __float2half_rn(tg[tx][ty + i * 8]);
        }
    }
}

// ---------------- router (+ x fp16 pack): one warp per token ----------------
__global__ void router_kernel(const float* __restrict__ x,
                              const float* __restrict__ rw,
                              const float* __restrict__ rb,
                              float* __restrict__ probs_out,
                              float* __restrict__ idx_out) {
    {
        size_t base = (size_t)blockIdx.x * 4 * DMODEL;
        const float2* src = (const float2*)(x + base);
        __half2* dst = (__half2*)(g_x_h + base);
        for (int i = threadIdx.x; i < 4 * DMODEL / 2; i += 128) {
            float2 v = src[i];
            dst[i] = __floats2half2_rn(v.x, v.y);
        }
    }

    int warp = (blockIdx.x * blockDim.x + threadIdx.x) >> 5;
    int lane = threadIdx.x & 31;
    if (warp >= NTOK) return;
    const float* xr = x + (size_t)warp * DMODEL;

    float acc[NEXP];
    #pragma unroll
    for (int e = 0; e < NEXP; e++) acc[e] = 0.f;

    for (int d = lane; d < DMODEL; d += 32) {
        float xv = xr[d];
        const float4* w4 = reinterpret_cast<const float4*>(rw + (size_t)d * NEXP);
        float4 w0 = w4[0], w1 = w4[1];
        acc[0] += xv * w0.x; acc[1] += xv * w0.y; acc[2] += xv * w0.z; acc[3] += xv * w0.w;
        acc[4] += xv * w1.x; acc[5] += xv * w1.y; acc[6] += xv * w1.z; acc[7] += xv * w1.w;
    }
    #pragma unroll
    for (int e = 0; e < NEXP; e++) {
        #pragma unroll
        for (int o = 16; o > 0; o >>= 1) acc[e] += __shfl_xor_sync(0xffffffffu, acc[e], o);
    }

    if (lane == 0) {
        float lg[NEXP];
        #pragma unroll
        for (int e = 0; e < NEXP; e++) lg[e] = acc[e] + rb[e];

        float m = lg[0];
        #pragma unroll
        for (int e = 1; e < NEXP; e++) m = fmaxf(m, lg[e]);
        float s = 0.f, p[NEXP];
        #pragma unroll
        for (int e = 0; e < NEXP; e++) { p[e] = expf(lg[e] - m); s += p[e]; }
        float inv = 1.f / s;
        #pragma unroll
        for (int e = 0; e < NEXP; e++) probs_out[(size_t)warp * NEXP + e] = p[e] * inv;

        int i0 = 0;
        #pragma unroll
        for (int e = 1; e < NEXP; e++) if (lg[e] > lg[i0]) i0 = e;
        int i1 = -1;
        #pragma unroll
        for (int e = 0; e < NEXP; e++) {
            if (e == i0) continue;
            if (i1 < 0 || lg[e] > lg[i1]) i1 = e;
        }
        float p0 = 1.f / (1.f + expf(lg[i1] - lg[i0]));
        float p1 = 1.f - p0;

        idx_out[warp * 2 + 0] = (float)i0;
        idx_out[warp * 2 + 1] = (float)i1;
        g_slot_e[warp * 2 + 0] = i0;
        g_slot_e[warp * 2 + 1] = i1;
        g_slot_w[warp * 2 + 0] = p0;
        g_slot_w[warp * 2 + 1] = p1;
        atomicAdd(&g_counts[i0], 1);
        atomicAdd(&g_counts[i1], 1);
    }
}

// ---------------- fused scan + list build ----------------
__global__ void finalize_kernel() {
    if (threadIdx.x == 0) {
        int off = 0;
        for (int e = 0; e < NEXP; e++) {
            g_offsets[e] = off;
            g_cursor[e]  = off;
            off += g_counts[e];
        }
        g_offsets[NEXP] = off;
    }
    __syncthreads();
    for (int t = threadIdx.x; t < NTOK; t += blockDim.x) {
        #pragma unroll
        for (int s = 0; s < 2; s++) {
            int e = g_slot_e[t * 2 + s];
            int pos = atomicAdd(&g_cursor[e], 1);
            g_row_token[pos] = t;
            g_row_w[pos] = g_slot_w[t * 2 + s];
        }
    }
}

// ---------------- GEMM1: H = silu(Xe@Wg+bg) * (Xe@Wu+bu) ----------------
// fp16 m16n8k16, ldmatrix fragments, 3-stage cp.async pipeline, one barrier/iter.
__global__ __launch_bounds__(256, 2)
void gemm1_kernel(const float* __restrict__ bg, const float* __restrict__ bu) {
    extern __shared__ char smem[];
    int e = blockIdx.z;
    int off = g_offsets[e];
    int ne = g_offsets[e + 1] - off;
    int mbase = blockIdx.x * BM;
    if (mbase >= ne) return;
    int n0 = blockIdx.y * BN;

    int tid = threadIdx.x;
    int lane = tid & 31, warp = tid >> 5;
    int wm = (warp & 3) * 32;
    int wn = (warp >> 2) * 32;

    // loaders: A row ra (0..127), half ah; B n-row rb8 (0..63), quarter bq
    int ra = tid >> 1;
    int ah = tid & 1;
    int ar = mbase + ra;
    const __half* gA  = g_x_h + (size_t)g_row_token[off + (ar < ne ? ar : 0)] * DMODEL + ah * 16;
    int rb8 = tid >> 2;
    int bq  = tid & 3;
    const __half* gBg = g_wg_h + ((size_t)e * DFF + n0 + rb8) * DMODEL + bq * 8;
    const __half* gBu = g_wu_h + ((size_t)e * DFF + n0 + rb8) * DMODEL + bq * 8;
    int daA = ra * PHB + ah * 32;
    int daB = rb8 * PHB + bq * 16;

    // ldmatrix lane addresses
    uint32_t sbase = (uint32_t)__cvta_generic_to_shared(smem);
    int rowa = ((lane >> 3) & 1) * 8 + (lane & 7);
    int koffa = (lane >> 4) * 16;            // bytes
    int rowb = (lane >> 4) * 8 + (lane & 7);
    int koffb = ((lane >> 3) & 1) * 16;      // bytes
    uint32_t aAddr[2], bgAddr[2], buAddr[2];
    #pragma unroll
    for (int mi = 0; mi < 2; mi++)
        aAddr[mi] = sbase + (wm + mi * 16 + rowa) * PHB + koffa;
    #pragma unroll
    for (int p = 0; p < 2; p++) {
        bgAddr[p] = sbase + G1_BG + (wn + p * 16 + rowb) * PHB + koffb;
        buAddr[p] = sbase + G1_BU + (wn + p * 16 + rowb) * PHB + koffb;
    }

    float accG[2][4][4], accU[2][4][4];
    #pragma unroll
    for (int mi = 0; mi < 2; mi++)
        #pragma unroll
        for (int ni = 0; ni < 4; ni++)
            #pragma unroll
            for (int q = 0; q < 4; q++) { accG[mi][ni][q] = 0.f; accU[mi][ni][q] = 0.f; }

    const int KT = DMODEL / BK;   // 32

    #define G1_PREFETCH(kt, st) do {                                   \
        char* b = smem + (st) * G1_STB;                                \
        const __half* a_ = gA + (kt) * BK;                             \
        cp16(b + daA,      a_);                                        \
        cp16(b + daA + 16, a_ + 8);                                    \
        cp16(b + G1_BG + daB, gBg + (kt) * BK);                        \
        cp16(b + G1_BU + daB, gBu + (kt) * BK);                        \
        CP_COMMIT();                                                   \
    } while (0)

    G1_PREFETCH(0, 0);
    G1_PREFETCH(1, 1);

    for (int kt = 0; kt < KT; kt++) {
        CP_WAIT(1);
        __syncthreads();
        if (kt + 2 < KT) G1_PREFETCH(kt + 2, (kt + 2) % G1_STAGES);
        else CP_COMMIT();   // keep group count exact for CP_WAIT(1)

        uint32_t so = (uint32_t)((kt % G1_STAGES) * G1_STB);
        #pragma unroll
        for (int ks = 0; ks < 2; ks++) {
            uint32_t kso = so + ks * 32;
            uint32_t af[2][4], bgf[2][4], buf[2][4];
            ldsm4(af[0], aAddr[0] + kso);
            ldsm4(af[1], aAddr[1] + kso);
            ldsm4(bgf[0], bgAddr[0] + kso);
            ldsm4(bgf[1], bgAddr[1] + kso);
            ldsm4(buf[0], buAddr[0] + kso);
            ldsm4(buf[1], buAddr[1] + kso);
            #pragma unroll
            for (int mi = 0; mi < 2; mi++)
                #pragma unroll
                for (int p = 0; p < 2; p++) {
                    mma_f16(accG[mi][2 * p],     af[mi], &bgf[p][0]);
                    mma_f16(accG[mi][2 * p + 1], af[mi], &bgf[p][2]);
                    mma_f16(accU[mi][2 * p],     af[mi], &buf[p][0]);
                    mma_f16(accU[mi][2 * p + 1], af[mi], &buf[p][2]);
                }
        }
    }
    #undef G1_PREFETCH

    // epilogue: silu(g)*u -> fp16 H (plain k-major)
    const float* bgp = bg + (size_t)e * DFF + n0;
    const float* bup = bu + (size_t)e * DFF + n0;
    #pragma unroll
    for (int mi = 0; mi < 2; mi++) {
        int r0 = mbase + wm + mi * 16 + (lane >> 2);
        #pragma unroll
        for (int ni = 0; ni < 4; ni++) {
            int nc = wn + ni * 8 + (lane & 3) * 2;
            float bg0 = bgp[nc], bg1 = bgp[nc + 1];
            float bu0 = bup[nc], bu1 = bup[nc + 1];
            if (r0 < ne) {
                size_t base = (size_t)(off + r0) * DFF + n0 + nc;
                float g = accG[mi][ni][0] + bg0, u = accU[mi][ni][0] + bu0;
                float h0 = (g / (1.f + expf(-g))) * u;
                g = accG[mi][ni][1] + bg1; u = accU[mi][ni][1] + bu1;
                float h1 = (g / (1.f + expf(-g))) * u;
                *(__half2*)(g_H_h + base) = __floats2half2_rn(h0, h1);
            }
            if (r0 + 8 < ne) {
                size_t base = (size_t)(off + r0 + 8) * DFF + n0 + nc;
                float g = accG[mi][ni][2] + bg0, u = accU[mi][ni][2] + bu0;
                float h0 = (g / (1.f + expf(-g))) * u;
                g = accG[mi][ni][3] + bg1; u = accU[mi][ni][3] + bu1;
                float h1 = (g / (1.f + expf(-g))) * u;
                *(__half2*)(g_H_h + base) = __floats2half2_rn(h0, h1);
            }
        }
    }
}

// ---------------- GEMM2: out[token] += w * (H_e @ Wd_e + bd) ----------------
// fp16 m16n8k16, ldmatrix fragments, 4-stage cp.async pipeline, one barrier/iter.
__global__ __launch_bounds__(256, 2)
void gemm2_kernel(const float* __restrict__ bd, float* __restrict__ out) {
    extern __shared__ char smem[];
    int e = blockIdx.z;
    int off = g_offsets[e];
    int ne = g_offsets[e + 1] - off;
    int mbase = blockIdx.x * BM;
    if (mbase >= ne) return;
    int n0 = blockIdx.y * BN;

    int tid = threadIdx.x;
    int lane = tid & 31, warp = tid >> 5;
    int wm = (warp & 3) * 32;
    int wn = (warp >> 2) * 32;

    int ra = tid >> 1;
    int ah = tid & 1;
    int ar = mbase + ra;
    const __half* gA = g_H_h + (size_t)(off + (ar < ne ? ar : 0)) * DFF + ah * 16;
    int rb8 = tid >> 2;
    int bq  = tid & 3;
    const __half* gB = g_wd_h + ((size_t)e * DMODEL + n0 + rb8) * DFF + bq * 8;
    int daA = ra * PHB + ah * 32;
    int daB = rb8 * PHB + bq * 16;

    uint32_t sbase = (uint32_t)__cvta_generic_to_shared(smem);
    int rowa = ((lane >> 3) & 1) * 8 + (lane & 7);
    int koffa = (lane >> 4) * 16;
    int rowb = (lane >> 4) * 8 + (lane & 7);
    int koffb = ((lane >> 3) & 1) * 16;
    uint32_t aAddr[2], bAddr[2];
    #pragma unroll
    for (int mi = 0; mi < 2; mi++)
        aAddr[mi] = sbase + (wm + mi * 16 + rowa) * PHB + koffa;
    #pragma unroll
    for (int p = 0; p < 2; p++)
        bAddr[p] = sbase + G2_BOFF + (wn + p * 16 + rowb) * PHB + koffb;

    float acc[2][4][4];
    #pragma unroll
    for (int mi = 0; mi < 2; mi++)
        #pragma unroll
        for (int ni = 0; ni < 4; ni++)
            #pragma unroll
            for (int q = 0; q < 4; q++) acc[mi][ni][q] = 0.f;

    const int KT = DFF / BK;   // 128

    #define G2_PREFETCH(kt, st) do {                                   \
        char* b = smem + (st) * G2_STB;                                \
        const __half* a_ = gA + (kt) * BK;                             \
        cp16(b + daA,      a_);                                        \
        cp16(b + daA + 16, a_ + 8);                                    \
        cp16(b + G2_BOFF + daB, gB + (kt) * BK);                       \
        CP_COMMIT();                                                   \
    } while (0)

    G2_PREFETCH(0, 0);
    G2_PREFETCH(1, 1);
    G2_PREFETCH(2, 2);

    for (int kt = 0; kt < KT; kt++) {
        CP_WAIT(2);
        __syncthreads();
        if (kt + 3 < KT) G2_PREFETCH(kt + 3, (kt + 3) % G2_STAGES);
        else CP_COMMIT();   // keep group count exact for CP_WAIT(2)

        uint32_t so = (uint32_t)((kt % G2_STAGES) * G2_STB);
        #pragma unroll
        for (int ks = 0; ks < 2; ks++) {
            uint32_t kso = so + ks * 32;
            uint32_t af[2][4], bf[2][4];
            ldsm4(af[0], aAddr[0] + kso);
            ldsm4(af[1], aAddr[1] + kso);
            ldsm4(bf[0], bAddr[0] + kso);
            ldsm4(bf[1], bAddr[1] + kso);
            #pragma unroll
            for (int mi = 0; mi < 2; mi++)
                #pragma unroll
                for (int p = 0; p < 2; p++) {
                    mma_f16(acc[mi][2 * p],     af[mi], &bf[p][0]);
                    mma_f16(acc[mi][2 * p + 1], af[mi], &bf[p][2]);
                }
        }
    }
    #undef G2_PREFETCH

    // epilogue: weighted scatter-add into out
    const float* bdp = bd + (size_t)e * DMODEL + n0;
    #pragma unroll
    for (int mi = 0; mi < 2; mi++) {
        int r0 = mbase + wm + mi * 16 + (lane >> 2);
        #pragma unroll
        for (int ni = 0; ni < 4; ni++) {
            int nc = wn + ni * 8 + (lane & 3) * 2;
            float b0 = bdp[nc], b1 = bdp[nc + 1];
            if (r0 < ne) {
                int tokr = g_row_token[off + r0];
                float w = g_row_w[off + r0];
                float* op = out + (size_t)tokr * DMODEL + n0 + nc;
                atomicAdd(op,     w * (acc[mi][ni][0] + b0));
                atomicAdd(op + 1, w * (acc[mi][ni][1] + b1));
            }
            if (r0 + 8 < ne) {
                int tokr = g_row_token[off + r0 + 8];
                float w = g_row_w[off + r0 + 8];
                float* op = out + (size_t)tokr * DMODEL + n0 + nc;
                atomicAdd(op,     w * (acc[mi][ni][2] + b0));
                atomicAdd(op + 1, w * (acc[mi][ni][3] + b1));
            }
        }
    }
}

// ---------------- launch ----------------
extern "C" void kernel_launch(void* const* d_in, const int* in_sizes, int n_in,
                              void* d_out, int out_size) {
    const float* x  = (const float*)d_in[0];
    const float* rw = (const float*)d_in[1];
    const float* rb = (const float*)d_in[2];
    const float* wg = (const float*)d_in[3];
    const float* bg = (const float*)d_in[4];
    const float* wu = (const float*)d_in[5];
    const float* bu = (const float*)d_in[6];
    const float* wd = (const float*)d_in[7];
    const float* bd = (const float*)d_in[8];

    float* out   = (float*)d_out;
    float* probs = out + (size_t)NTOK * DMODEL;
    float* idx   = probs + (size_t)NTOK * NEXP;

    cudaFuncSetAttribute(gemm1_kernel, cudaFuncAttributeMaxDynamicSharedMemorySize, G1_SMEM);
    cudaFuncSetAttribute(gemm2_kernel, cudaFuncAttributeMaxDynamicSharedMemorySize, G2_SMEM);

    cudaMemsetAsync(out, 0, (size_t)NTOK * DMODEL * sizeof(float));
    pack_w_kernel<<<dim3(128, 32, 16), dim3(32, 8)>>>(wg, wu, wd);
    router_kernel<<<NTOK / 4, 128>>>(x, rw, rb, probs, idx);
    finalize_kernel<<<1, 256>>>();
    gemm1_kernel<<<dim3(NTOK / BM, DFF / BN, NEXP), 256, G1_SMEM>>>(bg, bu);
    gemm2_kernel<<<dim3(NTOK / BM, DMODEL / BN, NEXP), 256, G2_SMEM>>>(bd, out);
}

// round 14
// speedup vs baseline: 2.2629x; 1.0976x over previous
#include <cuda_runtime.h>
#include <cuda_fp16.h>
#include <cstdint>
#include <math.h>

#define NTOK 4096
#define DMODEL 1024
#define NEXP 8
#define DFF 4096

#define BM 128
#define BN 64
#define BK 32            // 32 halves = 64 B per row per tile

#define PHB 80           // bytes per smem row (40 halves); 80i mod 128 covers 8 disjoint 16B spans
#define G1_BG 10240      // A: 128*80
#define G1_BU 15360      // + Bg: 64*80
#define G1_STB 20480     // stage bytes
#define G2_BOFF 10240
#define G2_STB 15360
#define G1_STAGES 4
#define G1_PF 3
#define G2_STAGES 5
#define G2_PF 4
#define G1_SMEM (G1_STAGES * G1_STB)   // 81920
#define G2_SMEM (G2_STAGES * G2_STB)   // 76800

// ---------------- scratch (static device globals; no allocation) ----------------
__device__ int   g_counts[NEXP];
__device__ int   g_offsets[NEXP + 1];
__device__ int   g_cursor[NEXP];
__device__ int   g_slot_e[NTOK * 2];
__device__ float g_slot_w[NTOK * 2];
__device__ int   g_row_token[NTOK * 2];
__device__ float g_row_w[NTOK * 2];

__device__ __align__(16) __half g_x_h [(size_t)NTOK * DMODEL];          // fp16, k-major
__device__ __align__(16) __half g_wg_h[(size_t)NEXP * DFF * DMODEL];    // fp16, n-major [e][n][k]
__device__ __align__(16) __half g_wu_h[(size_t)NEXP * DFF * DMODEL];    // fp16, n-major [e][n][k]
__device__ __align__(16) __half g_wd_h[(size_t)NEXP * DMODEL * DFF];    // fp16, n-major [e][n][k]
__device__ __align__(16) __half g_H_h [(size_t)NTOK * 2 * DFF];         // fp16, k-major

// ---------------- helpers ----------------
__device__ __forceinline__ void mma_f16(float c[4], const uint32_t a[4], const uint32_t b[2]) {
    asm volatile(
        "mma.sync.aligned.m16n8k16.row.col.f32.f16.f16.f32 "
        "{%0,%1,%2,%3}, {%4,%5,%6,%7}, {%8,%9}, {%0,%1,%2,%3};"
        : "+f"(c[0]), "+f"(c[1]), "+f"(c[2]), "+f"(c[3])
        : "r"(a[0]), "r"(a[1]), "r"(a[2]), "r"(a[3]), "r"(b[0]), "r"(b[1]));
}

__device__ __forceinline__ void ldsm4(uint32_t* r, uint32_t addr) {
    asm volatile("ldmatrix.sync.aligned.m8n8.x4.shared.b16 {%0,%1,%2,%3}, [%4];"
        : "=r"(r[0]), "=r"(r[1]), "=r"(r[2]), "=r"(r[3]) : "r"(addr));
}

__device__ __forceinline__ void cp16(void* dst, const void* src) {
    uint32_t d = (uint32_t)__cvta_generic_to_shared(dst);
    asm volatile("cp.async.cg.shared.global [%0], [%1], 16;" :: "r"(d), "l"(src));
}
#define CP_COMMIT() asm volatile("cp.async.commit_group;" ::: "memory")
#define CP_WAIT(n)  asm volatile("cp.async.wait_group %0;" :: "n"(n) : "memory")

// ---------------- pack: fp16-convert + transpose weights to n-major ----------------
__global__ void pack_w_kernel(const float* __restrict__ wg,
                              const float* __restrict__ wu,
                              const float* __restrict__ wd) {
    __shared__ float tg[32][33];
    __shared__ float tu[32][33];
    int z = blockIdx.z;
    int tx = threadIdx.x, ty = threadIdx.y;
    if (z == 0 && blockIdx.x == 0 && blockIdx.y == 0 && ty == 0 && tx < NEXP)
        g_counts[tx] = 0;

    if (z < 8) {
        size_t e = z;
        size_t kb = (size_t)blockIdx.y * 32, nb = (size_t)blockIdx.x * 32;
        #pragma unroll
        for (int i = 0; i < 4; i++) {
            size_t k = kb + ty + i * 8;
            tg[ty + i * 8][tx] = wg[(e * DMODEL + k) * DFF + nb + tx];
            tu[ty + i * 8][tx] = wu[(e * DMODEL + k) * DFF + nb + tx];
        }
        __syncthreads();
        #pragma unroll
        for (int i = 0; i < 4; i++) {
            size_t n = nb + ty + i * 8;
            g_wg_h[(e * DFF + n) * DMODEL + kb + tx] = __float2half_rn(tg[tx][ty + i * 8]);
            g_wu_h[(e * DFF + n) * DMODEL + kb + tx] = __float2half_rn(tu[tx][ty + i * 8]);
        }
    } else {
        size_t e = z - 8;
        size_t kb = (size_t)blockIdx.x * 32, nb = (size_t)blockIdx.y * 32;
        #pragma unroll
        for (int i = 0; i < 4; i++) {
            size_t k = kb + ty + i * 8;
            tg[ty + i * 8][tx] = wd[(e * DFF + k) * DMODEL + nb + tx];
        }
        __syncthreads();
        #pragma unroll
        for (int i = 0; i < 4; i++) {
            size_t n = nb + ty + i * 8;
            g_wd_h[(e * DMODEL + n) * DFF + kb + tx] = __float2half_rn(tg[tx][ty + i * 8]);
        }
    }
}

// ---------------- router (+ x fp16 pack): one warp per token ----------------
__global__ void router_kernel(const float* __restrict__ x,
                              const float* __restrict__ rw,
                              const float* __restrict__ rb,
                              float* __restrict__ probs_out,
                              float* __restrict__ idx_out) {
    {
        size_t base = (size_t)blockIdx.x * 4 * DMODEL;
        const float2* src = (const float2*)(x + base);
        __half2* dst = (__half2*)(g_x_h + base);
        for (int i = threadIdx.x; i < 4 * DMODEL / 2; i += 128) {
            float2 v = src[i];
            dst[i] = __floats2half2_rn(v.x, v.y);
        }
    }

    int warp = (blockIdx.x * blockDim.x + threadIdx.x) >> 5;
    int lane = threadIdx.x & 31;
    if (warp >= NTOK) return;
    const float* xr = x + (size_t)warp * DMODEL;

    float acc[NEXP];
    #pragma unroll
    for (int e = 0; e < NEXP; e++) acc[e] = 0.f;

    for (int d = lane; d < DMODEL; d += 32) {
        float xv = xr[d];
        const float4* w4 = reinterpret_cast<const float4*>(rw + (size_t)d * NEXP);
        float4 w0 = w4[0], w1 = w4[1];
        acc[0] += xv * w0.x; acc[1] += xv * w0.y; acc[2] += xv * w0.z; acc[3] += xv * w0.w;
        acc[4] += xv * w1.x; acc[5] += xv * w1.y; acc[6] += xv * w1.z; acc[7] += xv * w1.w;
    }
    #pragma unroll
    for (int e = 0; e < NEXP; e++) {
        #pragma unroll
        for (int o = 16; o > 0; o >>= 1) acc[e] += __shfl_xor_sync(0xffffffffu, acc[e], o);
    }

    if (lane == 0) {
        float lg[NEXP];
        #pragma unroll
        for (int e = 0; e < NEXP; e++) lg[e] = acc[e] + rb[e];

        float m = lg[0];
        #pragma unroll
        for (int e = 1; e < NEXP; e++) m = fmaxf(m, lg[e]);
        float s = 0.f, p[NEXP];
        #pragma unroll
        for (int e = 0; e < NEXP; e++) { p[e] = expf(lg[e] - m); s += p[e]; }
        float inv = 1.f / s;
        #pragma unroll
        for (int e = 0; e < NEXP; e++) probs_out[(size_t)warp * NEXP + e] = p[e] * inv;

        int i0 = 0;
        #pragma unroll
        for (int e = 1; e < NEXP; e++) if (lg[e] > lg[i0]) i0 = e;
        int i1 = -1;
        #pragma unroll
        for (int e = 0; e < NEXP; e++) {
            if (e == i0) continue;
            if (i1 < 0 || lg[e] > lg[i1]) i1 = e;
        }
        float p0 = 1.f / (1.f + expf(lg[i1] - lg[i0]));
        float p1 = 1.f - p0;

        idx_out[warp * 2 + 0] = (float)i0;
        idx_out[warp * 2 + 1] = (float)i1;
        g_slot_e[warp * 2 + 0] = i0;
        g_slot_e[warp * 2 + 1] = i1;
        g_slot_w[warp * 2 + 0] = p0;
        g_slot_w[warp * 2 + 1] = p1;
        atomicAdd(&g_counts[i0], 1);
        atomicAdd(&g_counts[i1], 1);
    }
}

// ---------------- fused scan + list build ----------------
__global__ void finalize_kernel() {
    if (threadIdx.x == 0) {
        int off = 0;
        for (int e = 0; e < NEXP; e++) {
            g_offsets[e] = off;
            g_cursor[e]  = off;
            off += g_counts[e];
        }
        g_offsets[NEXP] = off;
    }
    __syncthreads();
    for (int t = threadIdx.x; t < NTOK; t += blockDim.x) {
        #pragma unroll
        for (int s = 0; s < 2; s++) {
            int e = g_slot_e[t * 2 + s];
            int pos = atomicAdd(&g_cursor[e], 1);
            g_row_token[pos] = t;
            g_row_w[pos] = g_slot_w[t * 2 + s];
        }
    }
}

// ---------------- GEMM1: H = silu(Xe@Wg+bg) * (Xe@Wu+bu) ----------------
// fp16 m16n8k16, 4-stage cp.async pipeline; body order: LDSM(ks0) -> prefetch -> MMA(ks0) -> ks1.
__global__ __launch_bounds__(256, 2)
void gemm1_kernel(const float* __restrict__ bg, const float* __restrict__ bu) {
    extern __shared__ char smem[];
    int e = blockIdx.z;
    int off = g_offsets[e];
    int ne = g_offsets[e + 1] - off;
    int mbase = blockIdx.x * BM;
    if (mbase >= ne) return;
    int n0 = blockIdx.y * BN;

    int tid = threadIdx.x;
    int lane = tid & 31, warp = tid >> 5;
    int wm = (warp & 3) * 32;
    int wn = (warp >> 2) * 32;

    // loaders: A row ra (0..127), half ah; B n-row rb8 (0..63), quarter bq
    int ra = tid >> 1;
    int ah = tid & 1;
    int ar = mbase + ra;
    const __half* gA  = g_x_h + (size_t)g_row_token[off + (ar < ne ? ar : 0)] * DMODEL + ah * 16;
    int rb8 = tid >> 2;
    int bq  = tid & 3;
    const __half* gBg = g_wg_h + ((size_t)e * DFF + n0 + rb8) * DMODEL + bq * 8;
    const __half* gBu = g_wu_h + ((size_t)e * DFF + n0 + rb8) * DMODEL + bq * 8;
    int daA = ra * PHB + ah * 32;
    int daB = rb8 * PHB + bq * 16;

    // ldmatrix lane addresses
    uint32_t sbase = (uint32_t)__cvta_generic_to_shared(smem);
    int rowa = ((lane >> 3) & 1) * 8 + (lane & 7);
    int koffa = (lane >> 4) * 16;            // bytes
    int rowb = (lane >> 4) * 8 + (lane & 7);
    int koffb = ((lane >> 3) & 1) * 16;      // bytes
    uint32_t aAddr[2], bgAddr[2], buAddr[2];
    #pragma unroll
    for (int mi = 0; mi < 2; mi++)
        aAddr[mi] = sbase + (wm + mi * 16 + rowa) * PHB + koffa;
    #pragma unroll
    for (int p = 0; p < 2; p++) {
        bgAddr[p] = sbase + G1_BG + (wn + p * 16 + rowb) * PHB + koffb;
        buAddr[p] = sbase + G1_BU + (wn + p * 16 + rowb) * PHB + koffb;
    }

    float accG[2][4][4], accU[2][4][4];
    #pragma unroll
    for (int mi = 0; mi < 2; mi++)
        #pragma unroll
        for (int ni = 0; ni < 4; ni++)
            #pragma unroll
            for (int q = 0; q < 4; q++) { accG[mi][ni][q] = 0.f; accU[mi][ni][q] = 0.f; }

    const int KT = DMODEL / BK;   // 32

    #define G1_PREFETCH(kt, st) do {                                   \
        char* b = smem + (st) * G1_STB;                                \
        const __half* a_ = gA + (kt) * BK;                             \
        cp16(b + daA,      a_);                                        \
        cp16(b + daA + 16, a_ + 8);                                    \
        cp16(b + G1_BG + daB, gBg + (kt) * BK);                        \
        cp16(b + G1_BU + daB, gBu + (kt) * BK);                        \
        CP_COMMIT();                                                   \
    } while (0)

    G1_PREFETCH(0, 0);
    G1_PREFETCH(1, 1);
    G1_PREFETCH(2, 2);

    for (int kt = 0; kt < KT; kt++) {
        CP_WAIT(G1_PF - 1);
        __syncthreads();
        uint32_t so = (uint32_t)((kt % G1_STAGES) * G1_STB);

        // ks0 fragment loads first (MMAs can start sooner; cp.async hides under MMA)
        uint32_t af0[2][4], bgf0[2][4], buf0[2][4];
        ldsm4(af0[0], aAddr[0] + so);
        ldsm4(af0[1], aAddr[1] + so);
        ldsm4(bgf0[0], bgAddr[0] + so);
        ldsm4(bgf0[1], bgAddr[1] + so);
        ldsm4(buf0[0], buAddr[0] + so);
        ldsm4(buf0[1], buAddr[1] + so);

        if (kt + G1_PF < KT) G1_PREFETCH(kt + G1_PF, (kt + G1_PF) % G1_STAGES);
        else CP_COMMIT();   // keep group count exact for CP_WAIT

        #pragma unroll
        for (int mi = 0; mi < 2; mi++)
            #pragma unroll
            for (int p = 0; p < 2; p++) {
                mma_f16(accG[mi][2 * p],     af0[mi], &bgf0[p][0]);
                mma_f16(accG[mi][2 * p + 1], af0[mi], &bgf0[p][2]);
                mma_f16(accU[mi][2 * p],     af0[mi], &buf0[p][0]);
                mma_f16(accU[mi][2 * p + 1], af0[mi], &buf0[p][2]);
            }

        // ks1
        uint32_t so1 = so + 32;
        uint32_t af1[2][4], bgf1[2][4], buf1[2][4];
        ldsm4(af1[0], aAddr[0] + so1);
        ldsm4(af1[1], aAddr[1] + so1);
        ldsm4(bgf1[0], bgAddr[0] + so1);
        ldsm4(bgf1[1], bgAddr[1] + so1);
        ldsm4(buf1[0], buAddr[0] + so1);
        ldsm4(buf1[1], buAddr[1] + so1);
        #pragma unroll
        for (int mi = 0; mi < 2; mi++)
            #pragma unroll
            for (int p = 0; p < 2; p++) {
                mma_f16(accG[mi][2 * p],     af1[mi], &bgf1[p][0]);
                mma_f16(accG[mi][2 * p + 1], af1[mi], &bgf1[p][2]);
                mma_f16(accU[mi][2 * p],     af1[mi], &buf1[p][0]);
                mma_f16(accU[mi][2 * p + 1], af1[mi], &buf1[p][2]);
            }
    }
    #undef G1_PREFETCH

    // epilogue: silu(g)*u -> fp16 H (plain k-major)
    const float* bgp = bg + (size_t)e * DFF + n0;
    const float* bup = bu + (size_t)e * DFF + n0;
    #pragma unroll
    for (int mi = 0; mi < 2; mi++) {
        int r0 = mbase + wm + mi * 16 + (lane >> 2);
        #pragma unroll
        for (int ni = 0; ni < 4; ni++) {
            int nc = wn + ni * 8 + (lane & 3) * 2;
            float bg0 = bgp[nc], bg1 = bgp[nc + 1];
            float bu0 = bup[nc], bu1 = bup[nc + 1];
            if (r0 < ne) {
                size_t base = (size_t)(off + r0) * DFF + n0 + nc;
                float g = accG[mi][ni][0] + bg0, u = accU[mi][ni][0] + bu0;
                float h0 = (g / (1.f + expf(-g))) * u;
                g = accG[mi][ni][1] + bg1; u = accU[mi][ni][1] + bu1;
                float h1 = (g / (1.f + expf(-g))) * u;
                *(__half2*)(g_H_h + base) = __floats2half2_rn(h0, h1);
            }
            if (r0 + 8 < ne) {
                size_t base = (size_t)(off + r0 + 8) * DFF + n0 + nc;
                float g = accG[mi][ni][2] + bg0, u = accU[mi][ni][2] + bu0;
                float h0 = (g / (1.f + expf(-g))) * u;
                g = accG[mi][ni][3] + bg1; u = accU[mi][ni][3] + bu1;
                float h1 = (g / (1.f + expf(-g))) * u;
                *(__half2*)(g_H_h + base) = __floats2half2_rn(h0, h1);
            }
        }
    }
}

// ---------------- GEMM2: out[token] += w * (H_e @ Wd_e + bd) ----------------
// fp16 m16n8k16, 5-stage cp.async pipeline; same body order.
__global__ __launch_bounds__(256, 2)
void gemm2_kernel(const float* __restrict__ bd, float* __restrict__ out) {
    extern __shared__ char smem[];
    int e = blockIdx.z;
    int off = g_offsets[e];
    int ne = g_offsets[e + 1] - off;
    int mbase = blockIdx.x * BM;
    if (mbase >= ne) return;
    int n0 = blockIdx.y * BN;

    int tid = threadIdx.x;
    int lane = tid & 31, warp = tid >> 5;
    int wm = (warp & 3) * 32;
    int wn = (warp >> 2) * 32;

    int ra = tid >> 1;
    int ah = tid & 1;
    int ar = mbase + ra;
    const __half* gA = g_H_h + (size_t)(off + (ar < ne ? ar : 0)) * DFF + ah * 16;
    int rb8 = tid >> 2;
    int bq  = tid & 3;
    const __half* gB = g_wd_h + ((size_t)e * DMODEL + n0 + rb8) * DFF + bq * 8;
    int daA = ra * PHB + ah * 32;
    int daB = rb8 * PHB + bq * 16;

    uint32_t sbase = (uint32_t)__cvta_generic_to_shared(smem);
    int rowa = ((lane >> 3) & 1) * 8 + (lane & 7);
    int koffa = (lane >> 4) * 16;
    int rowb = (lane >> 4) * 8 + (lane & 7);
    int koffb = ((lane >> 3) & 1) * 16;
    uint32_t aAddr[2], bAddr[2];
    #pragma unroll
    for (int mi = 0; mi < 2; mi++)
        aAddr[mi] = sbase + (wm + mi * 16 + rowa) * PHB + koffa;
    #pragma unroll
    for (int p = 0; p < 2; p++)
        bAddr[p] = sbase + G2_BOFF + (wn + p * 16 + rowb) * PHB + koffb;

    float acc[2][4][4];
    #pragma unroll
    for (int mi = 0; mi < 2; mi++)
        #pragma unroll
        for (int ni = 0; ni < 4; ni++)
            #pragma unroll
            for (int q = 0; q < 4; q++) acc[mi][ni][q] = 0.f;

    const int KT = DFF / BK;   // 128

    #define G2_PREFETCH(kt, st) do {                                   \
        char* b = smem + (st) * G2_STB;                                \
        const __half* a_ = gA + (kt) * BK;                             \
        cp16(b + daA,      a_);                                        \
        cp16(b + daA + 16, a_ + 8);                                    \
        cp16(b + G2_BOFF + daB, gB + (kt) * BK);                       \
        CP_COMMIT();                                                   \
    } while (0)

    G2_PREFETCH(0, 0);
    G2_PREFETCH(1, 1);
    G2_PREFETCH(2, 2);
    G2_PREFETCH(3, 3);

    for (int kt = 0; kt < KT; kt++) {
        CP_WAIT(G2_PF - 1);
        __syncthreads();
        uint32_t so = (uint32_t)((kt % G2_STAGES) * G2_STB);

        uint32_t af0[2][4], bf0[2][4];
        ldsm4(af0[0], aAddr[0] + so);
        ldsm4(af0[1], aAddr[1] + so);
        ldsm4(bf0[0], bAddr[0] + so);
        ldsm4(bf0[1], bAddr[1] + so);

        if (kt + G2_PF < KT) G2_PREFETCH(kt + G2_PF, (kt + G2_PF) % G2_STAGES);
        else CP_COMMIT();

        #pragma unroll
        for (int mi = 0; mi < 2; mi++)
            #pragma unroll
            for (int p = 0; p < 2; p++) {
                mma_f16(acc[mi][2 * p],     af0[mi], &bf0[p][0]);
                mma_f16(acc[mi][2 * p + 1], af0[mi], &bf0[p][2]);
            }

        uint32_t so1 = so + 32;
        uint32_t af1[2][4], bf1[2][4];
        ldsm4(af1[0], aAddr[0] + so1);
        ldsm4(af1[1], aAddr[1] + so1);
        ldsm4(bf1[0], bAddr[0] + so1);
        ldsm4(bf1[1], bAddr[1] + so1);
        #pragma unroll
        for (int mi = 0; mi < 2; mi++)
            #pragma unroll
            for (int p = 0; p < 2; p++) {
                mma_f16(acc[mi][2 * p],     af1[mi], &bf1[p][0]);
                mma_f16(acc[mi][2 * p + 1], af1[mi], &bf1[p][2]);
            }
    }
    #undef G2_PREFETCH

    // epilogue: weighted scatter-add into out
    const float* bdp = bd + (size_t)e * DMODEL + n0;
    #pragma unroll
    for (int mi = 0; mi < 2; mi++) {
        int r0 = mbase + wm + mi * 16 + (lane >> 2);
        #pragma unroll
        for (int ni = 0; ni < 4; ni++) {
            int nc = wn + ni * 8 + (lane & 3) * 2;
            float b0 = bdp[nc], b1 = bdp[nc + 1];
            if (r0 < ne) {
                int tokr = g_row_token[off + r0];
                float w = g_row_w[off + r0];
                float* op = out + (size_t)tokr * DMODEL + n0 + nc;
                atomicAdd(op,     w * (acc[mi][ni][0] + b0));
                atomicAdd(op + 1, w * (acc[mi][ni][1] + b1));
            }
            if (r0 + 8 < ne) {
                int tokr = g_row_token[off + r0 + 8];
                float w = g_row_w[off + r0 + 8];
                float* op = out + (size_t)tokr * DMODEL + n0 + nc;
                atomicAdd(op,     w * (acc[mi][ni][2] + b0));
                atomicAdd(op + 1, w * (acc[mi][ni][3] + b1));
            }
        }
    }
}

// ---------------- launch ----------------
extern "C" void kernel_launch(void* const* d_in, const int* in_sizes, int n_in,
                              void* d_out, int out_size) {
    const float* x  = (const float*)d_in[0];
    const float* rw = (const float*)d_in[1];
    const float* rb = (const float*)d_in[2];
    const float* wg = (const float*)d_in[3];
    const float* bg = (const float*)d_in[4];
    const float* wu = (const float*)d_in[5];
    const float* bu = (const float*)d_in[6];
    const float* wd = (const float*)d_in[7];
    const float* bd = (const float*)d_in[8];

    float* out   = (float*)d_out;
    float* probs = out + (size_t)NTOK * DMODEL;
    float* idx   = probs + (size_t)NTOK * NEXP;

    cudaFuncSetAttribute(gemm1_kernel, cudaFuncAttributeMaxDynamicSharedMemorySize, G1_SMEM);
    cudaFuncSetAttribute(gemm2_kernel, cudaFuncAttributeMaxDynamicSharedMemorySize, G2_SMEM);

    cudaMemsetAsync(out, 0, (size_t)NTOK * DMODEL * sizeof(float));
    pack_w_kernel<<<dim3(128, 32, 16), dim3(32, 8)>>>(wg, wu, wd);
    router_kernel<<<NTOK / 4, 128>>>(x, rw, rb, probs, idx);
    finalize_kernel<<<1, 256>>>();
    gemm1_kernel<<<dim3(NTOK / BM, DFF / BN, NEXP), 256, G1_SMEM>>>(bg, bu);
    gemm2_kernel<<<dim3(NTOK / BM, DMODEL / BN, NEXP), 256, G2_SMEM>>>(bd, out);
}